// round 1
// baseline (speedup 1.0000x reference)
#include <cuda_runtime.h>
#include <cstddef>

#define B_ 2
#define N_ 2048
#define C_ 1024
#define H_ 16
#define D_ 64
#define SCALE_ 0.125f

// Scratch (allocation-free rule: __device__ globals)
__device__ float g_q[(size_t)B_ * H_ * N_ * D_];   // [B][H][N][D], pre-scaled, +q_bias
__device__ float g_k[(size_t)B_ * H_ * N_ * D_];   // [B][H][N][D]
__device__ float g_v[(size_t)B_ * H_ * N_ * D_];   // [B][H][N][D], +v_bias
__device__ float g_o[(size_t)B_ * N_ * C_];        // [B][N][H*D]  (proj input)

// ---------------------------------------------------------------------------
// Kernel 1: QKV GEMM.  out[m][j] = sum_k x[m][k] * qkv_w[j][k] (+bias), split
// into q/k/v with [B,H,N,D] layout.  BM=128, BN=64, BK=16, 256 thr, 8x4/thr.
// Each 64-wide column block maps to exactly one (which, head).
// ---------------------------------------------------------------------------
__global__ __launch_bounds__(256) void qkv_gemm_kernel(
    const float* __restrict__ x, const float* __restrict__ w,
    const float* __restrict__ qb, const float* __restrict__ vb) {
    __shared__ float As[16][128];
    __shared__ float Bs[16][64];

    const int tid = threadIdx.x;
    const int tx = tid & 15, ty = tid >> 4;
    const int m0 = blockIdx.y * 128;
    const int n0 = blockIdx.x * 64;

    const float* Abase = x + (size_t)m0 * C_;
    const float* Bbase = w + (size_t)n0 * C_;

    float acc[8][4];
#pragma unroll
    for (int i = 0; i < 8; i++)
#pragma unroll
        for (int j = 0; j < 4; j++) acc[i][j] = 0.f;

    for (int k0 = 0; k0 < C_; k0 += 16) {
        // load A tile 128x16 (2 float4 per thread)
        {
            int idx = tid;
#pragma unroll
            for (int rep = 0; rep < 2; rep++) {
                int row = idx >> 2;
                int kq = idx & 3;
                float4 v = *(const float4*)(Abase + (size_t)row * C_ + k0 + kq * 4);
                As[kq * 4 + 0][row] = v.x;
                As[kq * 4 + 1][row] = v.y;
                As[kq * 4 + 2][row] = v.z;
                As[kq * 4 + 3][row] = v.w;
                idx += 256;
            }
        }
        // load B tile 64x16 (1 float4 per thread)
        {
            int n = tid >> 2, kq = tid & 3;
            float4 v = *(const float4*)(Bbase + (size_t)n * C_ + k0 + kq * 4);
            Bs[kq * 4 + 0][n] = v.x;
            Bs[kq * 4 + 1][n] = v.y;
            Bs[kq * 4 + 2][n] = v.z;
            Bs[kq * 4 + 3][n] = v.w;
        }
        __syncthreads();
#pragma unroll
        for (int kk = 0; kk < 16; kk++) {
            float a[8], b[4];
            *(float4*)&a[0] = *(const float4*)&As[kk][ty * 8];
            *(float4*)&a[4] = *(const float4*)&As[kk][ty * 8 + 4];
            *(float4*)&b[0] = *(const float4*)&Bs[kk][tx * 4];
#pragma unroll
            for (int i = 0; i < 8; i++)
#pragma unroll
                for (int j = 0; j < 4; j++) acc[i][j] += a[i] * b[j];
        }
        __syncthreads();
    }

    // epilogue: route to q/k/v scratch
    const int which = n0 / C_;       // 0=q, 1=k, 2=v
    const int ch0 = n0 % C_;
    const int h = ch0 / D_;          // whole 64-col block is one head
    float* dst = (which == 0) ? g_q : (which == 1 ? g_k : g_v);

#pragma unroll
    for (int i = 0; i < 8; i++) {
        const int m = m0 + ty * 8 + i;
        const int b = m / N_;
        const int n = m % N_;
        float* drow = dst + (((size_t)(b * H_ + h) * N_ + n) * D_);
        float4 o4;
        float v0 = acc[i][0], v1 = acc[i][1], v2 = acc[i][2], v3 = acc[i][3];
        const int d0 = tx * 4;
        if (which == 0) {
            v0 = (v0 + qb[ch0 + d0 + 0]) * SCALE_;
            v1 = (v1 + qb[ch0 + d0 + 1]) * SCALE_;
            v2 = (v2 + qb[ch0 + d0 + 2]) * SCALE_;
            v3 = (v3 + qb[ch0 + d0 + 3]) * SCALE_;
        } else if (which == 2) {
            v0 += vb[ch0 + d0 + 0];
            v1 += vb[ch0 + d0 + 1];
            v2 += vb[ch0 + d0 + 2];
            v3 += vb[ch0 + d0 + 3];
        }
        o4.x = v0; o4.y = v1; o4.z = v2; o4.w = v3;
        *(float4*)(drow + d0) = o4;
    }
}

// ---------------------------------------------------------------------------
// Kernel 2: fused flash attention with rel-pos bias.
// Grid: (B*H, N/128). CTA: 128 Q-rows x full D=64, key tiles of 64.
// Scores in registers (8x4 per thread), online softmax, PV via smem P buffer.
// ---------------------------------------------------------------------------
__global__ __launch_bounds__(256, 1) void attn_kernel(const float* __restrict__ bias) {
    extern __shared__ float sm[];
    float* Qt = sm;                    // [64][128]  Q transposed (d-major)
    float* Kt = Qt + 64 * 128;         // [64][68]   K transposed (d-major), padded
    float* Vs = Kt + 64 * 68;          // [64][68]   V natural (key-major), padded
    float* Ps = Vs + 64 * 68;          // [128][68]  P (softmaxed scores), padded

    const int tid = threadIdx.x;
    const int tx = tid & 15, ty = tid >> 4;
    const int bh = blockIdx.x;                 // b*H + h
    const int h = bh % H_;
    const int b = bh / H_;
    const int q0 = blockIdx.y * 128;

    const float* qptr = g_q + ((size_t)bh * N_ + q0) * D_;
    const float* kbase = g_k + (size_t)bh * N_ * D_;
    const float* vbase = g_v + (size_t)bh * N_ * D_;
    const float* brow = bias + ((size_t)h * N_ + q0) * N_;

    // load Q tile transposed: Qt[d][r]
    for (int idx = tid; idx < 128 * 16; idx += 256) {
        int r = idx >> 4;
        int dq = idx & 15;
        float4 v = *(const float4*)(qptr + (size_t)r * D_ + dq * 4);
        Qt[(dq * 4 + 0) * 128 + r] = v.x;
        Qt[(dq * 4 + 1) * 128 + r] = v.y;
        Qt[(dq * 4 + 2) * 128 + r] = v.z;
        Qt[(dq * 4 + 3) * 128 + r] = v.w;
    }

    float m_i[8], l_i[8], acc[8][4];
#pragma unroll
    for (int i = 0; i < 8; i++) {
        m_i[i] = -1e30f;
        l_i[i] = 0.f;
#pragma unroll
        for (int j = 0; j < 4; j++) acc[i][j] = 0.f;
    }

    for (int kt = 0; kt < N_; kt += 64) {
        __syncthreads();  // prior PV done reading Kt/Vs/Ps, Q load done (1st iter)
        // load K tile transposed: Kt[d][c]
        for (int idx = tid; idx < 64 * 16; idx += 256) {
            int c = idx >> 4;
            int dq = idx & 15;
            float4 v = *(const float4*)(kbase + (size_t)(kt + c) * D_ + dq * 4);
            Kt[(dq * 4 + 0) * 68 + c] = v.x;
            Kt[(dq * 4 + 1) * 68 + c] = v.y;
            Kt[(dq * 4 + 2) * 68 + c] = v.z;
            Kt[(dq * 4 + 3) * 68 + c] = v.w;
        }
        // load V tile natural: Vs[c][d]
        for (int idx = tid; idx < 64 * 16; idx += 256) {
            int c = idx >> 4;
            int dq = idx & 15;
            float4 v = *(const float4*)(vbase + (size_t)(kt + c) * D_ + dq * 4);
            *(float4*)&Vs[c * 68 + dq * 4] = v;
        }
        __syncthreads();

        // S = Q K^T   (q pre-scaled)
        float s[8][4];
#pragma unroll
        for (int i = 0; i < 8; i++)
#pragma unroll
            for (int j = 0; j < 4; j++) s[i][j] = 0.f;

#pragma unroll 8
        for (int kk = 0; kk < 64; kk++) {
            float a[8], bv[4];
            *(float4*)&a[0] = *(const float4*)&Qt[kk * 128 + ty * 8];
            *(float4*)&a[4] = *(const float4*)&Qt[kk * 128 + ty * 8 + 4];
            *(float4*)&bv[0] = *(const float4*)&Kt[kk * 68 + tx * 4];
#pragma unroll
            for (int i = 0; i < 8; i++)
#pragma unroll
                for (int j = 0; j < 4; j++) s[i][j] += a[i] * bv[j];
        }

        // + rel_pos_bias, online softmax, write P
#pragma unroll
        for (int i = 0; i < 8; i++) {
            float4 bv = *(const float4*)(brow + (size_t)(ty * 8 + i) * N_ + kt + tx * 4);
            s[i][0] += bv.x; s[i][1] += bv.y; s[i][2] += bv.z; s[i][3] += bv.w;

            float mx = fmaxf(fmaxf(s[i][0], s[i][1]), fmaxf(s[i][2], s[i][3]));
#pragma unroll
            for (int off = 1; off < 16; off <<= 1)
                mx = fmaxf(mx, __shfl_xor_sync(0xffffffffu, mx, off));
            float m_new = fmaxf(m_i[i], mx);
            float sf = __expf(m_i[i] - m_new);
            float rs = 0.f;
#pragma unroll
            for (int j = 0; j < 4; j++) {
                s[i][j] = __expf(s[i][j] - m_new);
                rs += s[i][j];
            }
#pragma unroll
            for (int off = 1; off < 16; off <<= 1)
                rs += __shfl_xor_sync(0xffffffffu, rs, off);
            l_i[i] = l_i[i] * sf + rs;
            m_i[i] = m_new;
#pragma unroll
            for (int j = 0; j < 4; j++) acc[i][j] *= sf;
            *(float4*)&Ps[(ty * 8 + i) * 68 + tx * 4] = *(float4*)&s[i][0];
        }
        __syncthreads();

        // O += P V
#pragma unroll 8
        for (int kk = 0; kk < 64; kk++) {
            float vv[4];
            *(float4*)&vv[0] = *(const float4*)&Vs[kk * 68 + tx * 4];
#pragma unroll
            for (int i = 0; i < 8; i++) {
                float p = Ps[(ty * 8 + i) * 68 + kk];
#pragma unroll
                for (int j = 0; j < 4; j++) acc[i][j] += p * vv[j];
            }
        }
    }

    // normalize + store to g_o in [B][N][H*D]
#pragma unroll
    for (int i = 0; i < 8; i++) {
        float inv = 1.f / l_i[i];
        int n = q0 + ty * 8 + i;
        float4 o4;
        o4.x = acc[i][0] * inv;
        o4.y = acc[i][1] * inv;
        o4.z = acc[i][2] * inv;
        o4.w = acc[i][3] * inv;
        *(float4*)(g_o + ((size_t)(b * N_ + n) * C_) + h * D_ + tx * 4) = o4;
    }
}

// ---------------------------------------------------------------------------
// Kernel 3: output projection GEMM: out = g_o @ proj_w^T + proj_b
// Same structure as kernel 1.  Grid (1024/64, 4096/128).
// ---------------------------------------------------------------------------
__global__ __launch_bounds__(256) void proj_gemm_kernel(
    const float* __restrict__ w, const float* __restrict__ pb,
    float* __restrict__ out) {
    __shared__ float As[16][128];
    __shared__ float Bs[16][64];

    const int tid = threadIdx.x;
    const int tx = tid & 15, ty = tid >> 4;
    const int m0 = blockIdx.y * 128;
    const int n0 = blockIdx.x * 64;

    const float* Abase = g_o + (size_t)m0 * C_;
    const float* Bbase = w + (size_t)n0 * C_;

    float acc[8][4];
#pragma unroll
    for (int i = 0; i < 8; i++)
#pragma unroll
        for (int j = 0; j < 4; j++) acc[i][j] = 0.f;

    for (int k0 = 0; k0 < C_; k0 += 16) {
        {
            int idx = tid;
#pragma unroll
            for (int rep = 0; rep < 2; rep++) {
                int row = idx >> 2;
                int kq = idx & 3;
                float4 v = *(const float4*)(Abase + (size_t)row * C_ + k0 + kq * 4);
                As[kq * 4 + 0][row] = v.x;
                As[kq * 4 + 1][row] = v.y;
                As[kq * 4 + 2][row] = v.z;
                As[kq * 4 + 3][row] = v.w;
                idx += 256;
            }
        }
        {
            int n = tid >> 2, kq = tid & 3;
            float4 v = *(const float4*)(Bbase + (size_t)n * C_ + k0 + kq * 4);
            Bs[kq * 4 + 0][n] = v.x;
            Bs[kq * 4 + 1][n] = v.y;
            Bs[kq * 4 + 2][n] = v.z;
            Bs[kq * 4 + 3][n] = v.w;
        }
        __syncthreads();
#pragma unroll
        for (int kk = 0; kk < 16; kk++) {
            float a[8], b[4];
            *(float4*)&a[0] = *(const float4*)&As[kk][ty * 8];
            *(float4*)&a[4] = *(const float4*)&As[kk][ty * 8 + 4];
            *(float4*)&b[0] = *(const float4*)&Bs[kk][tx * 4];
#pragma unroll
            for (int i = 0; i < 8; i++)
#pragma unroll
                for (int j = 0; j < 4; j++) acc[i][j] += a[i] * b[j];
        }
        __syncthreads();
    }

#pragma unroll
    for (int i = 0; i < 8; i++) {
        const int m = m0 + ty * 8 + i;
        const int n = n0 + tx * 4;
        float4 o4;
        o4.x = acc[i][0] + pb[n + 0];
        o4.y = acc[i][1] + pb[n + 1];
        o4.z = acc[i][2] + pb[n + 2];
        o4.w = acc[i][3] + pb[n + 3];
        *(float4*)(out + (size_t)m * C_ + n) = o4;
    }
}

// ---------------------------------------------------------------------------
extern "C" void kernel_launch(void* const* d_in, const int* in_sizes, int n_in,
                              void* d_out, int out_size) {
    const float* x      = (const float*)d_in[0];   // [B,N,C]
    const float* bias   = (const float*)d_in[1];   // [H,N,N]
    const float* qkv_w  = (const float*)d_in[2];   // [3C,C]
    const float* q_bias = (const float*)d_in[3];   // [C]
    const float* v_bias = (const float*)d_in[4];   // [C]
    const float* proj_w = (const float*)d_in[5];   // [C,C]
    const float* proj_b = (const float*)d_in[6];   // [C]
    float* out = (float*)d_out;                    // [B,N,C]

    const int attn_smem = 102400;  // 100 KB dynamic
    cudaFuncSetAttribute(attn_kernel, cudaFuncAttributeMaxDynamicSharedMemorySize,
                         attn_smem);

    qkv_gemm_kernel<<<dim3(3 * C_ / 64, B_ * N_ / 128), 256>>>(x, qkv_w, q_bias, v_bias);
    attn_kernel<<<dim3(B_ * H_, N_ / 128), 256, attn_smem>>>(bias);
    proj_gemm_kernel<<<dim3(C_ / 64, B_ * N_ / 128), 256>>>(proj_w, proj_b, out);
}

// round 2
// speedup vs baseline: 1.0020x; 1.0020x over previous
#include <cuda_runtime.h>
#include <cstddef>

#define B_ 2
#define N_ 2048
#define C_ 1024
#define H_ 16
#define D_ 64
#define SCALE_ 0.125f

// Scratch (allocation-free rule: __device__ globals)
__device__ float g_q[(size_t)B_ * H_ * N_ * D_];   // [B][H][N][D], pre-scaled, +q_bias
__device__ float g_k[(size_t)B_ * H_ * N_ * D_];   // [B][H][N][D]
__device__ float g_v[(size_t)B_ * H_ * N_ * D_];   // [B][H][N][D], +v_bias
__device__ float g_o[(size_t)B_ * N_ * C_];        // [B][N][H*D]  (proj input)

// ---------------------------------------------------------------------------
// Kernel 1: QKV GEMM.  out[m][j] = sum_k x[m][k] * qkv_w[j][k] (+bias), split
// into q/k/v with [B,H,N,D] layout.  BM=128, BN=64, BK=16, 256 thr, 8x4/thr.
// Each 64-wide column block maps to exactly one (which, head).
// ---------------------------------------------------------------------------
__global__ __launch_bounds__(256) void qkv_gemm_kernel(
    const float* __restrict__ x, const float* __restrict__ w,
    const float* __restrict__ qb, const float* __restrict__ vb) {
    __shared__ float As[16][128];
    __shared__ float Bs[16][64];

    const int tid = threadIdx.x;
    const int tx = tid & 15, ty = tid >> 4;
    const int m0 = blockIdx.y * 128;
    const int n0 = blockIdx.x * 64;

    const float* Abase = x + (size_t)m0 * C_;
    const float* Bbase = w + (size_t)n0 * C_;

    float acc[8][4];
#pragma unroll
    for (int i = 0; i < 8; i++)
#pragma unroll
        for (int j = 0; j < 4; j++) acc[i][j] = 0.f;

    for (int k0 = 0; k0 < C_; k0 += 16) {
        // load A tile 128x16 (2 float4 per thread)
        {
            int idx = tid;
#pragma unroll
            for (int rep = 0; rep < 2; rep++) {
                int row = idx >> 2;
                int kq = idx & 3;
                float4 v = *(const float4*)(Abase + (size_t)row * C_ + k0 + kq * 4);
                As[kq * 4 + 0][row] = v.x;
                As[kq * 4 + 1][row] = v.y;
                As[kq * 4 + 2][row] = v.z;
                As[kq * 4 + 3][row] = v.w;
                idx += 256;
            }
        }
        // load B tile 64x16 (1 float4 per thread)
        {
            int n = tid >> 2, kq = tid & 3;
            float4 v = *(const float4*)(Bbase + (size_t)n * C_ + k0 + kq * 4);
            Bs[kq * 4 + 0][n] = v.x;
            Bs[kq * 4 + 1][n] = v.y;
            Bs[kq * 4 + 2][n] = v.z;
            Bs[kq * 4 + 3][n] = v.w;
        }
        __syncthreads();
#pragma unroll
        for (int kk = 0; kk < 16; kk++) {
            float a[8], b[4];
            *(float4*)&a[0] = *(const float4*)&As[kk][ty * 8];
            *(float4*)&a[4] = *(const float4*)&As[kk][ty * 8 + 4];
            *(float4*)&b[0] = *(const float4*)&Bs[kk][tx * 4];
#pragma unroll
            for (int i = 0; i < 8; i++)
#pragma unroll
                for (int j = 0; j < 4; j++) acc[i][j] += a[i] * b[j];
        }
        __syncthreads();
    }

    // epilogue: route to q/k/v scratch
    const int which = n0 / C_;       // 0=q, 1=k, 2=v
    const int ch0 = n0 % C_;
    const int h = ch0 / D_;          // whole 64-col block is one head
    float* dst = (which == 0) ? g_q : (which == 1 ? g_k : g_v);

#pragma unroll
    for (int i = 0; i < 8; i++) {
        const int m = m0 + ty * 8 + i;
        const int b = m / N_;
        const int n = m % N_;
        float* drow = dst + (((size_t)(b * H_ + h) * N_ + n) * D_);
        float4 o4;
        float v0 = acc[i][0], v1 = acc[i][1], v2 = acc[i][2], v3 = acc[i][3];
        const int d0 = tx * 4;
        if (which == 0) {
            v0 = (v0 + qb[ch0 + d0 + 0]) * SCALE_;
            v1 = (v1 + qb[ch0 + d0 + 1]) * SCALE_;
            v2 = (v2 + qb[ch0 + d0 + 2]) * SCALE_;
            v3 = (v3 + qb[ch0 + d0 + 3]) * SCALE_;
        } else if (which == 2) {
            v0 += vb[ch0 + d0 + 0];
            v1 += vb[ch0 + d0 + 1];
            v2 += vb[ch0 + d0 + 2];
            v3 += vb[ch0 + d0 + 3];
        }
        o4.x = v0; o4.y = v1; o4.z = v2; o4.w = v3;
        *(float4*)(drow + d0) = o4;
    }
}

// ---------------------------------------------------------------------------
// Kernel 2: fused flash attention with rel-pos bias.
// Grid: (B*H, N/128). CTA: 128 Q-rows x full D=64, key tiles of 64.
// Scores in registers (8x4 per thread), online softmax, PV via smem P buffer.
// ---------------------------------------------------------------------------
__global__ __launch_bounds__(256, 1) void attn_kernel(const float* __restrict__ bias) {
    extern __shared__ float sm[];
    float* Qt = sm;                    // [64][128]  Q transposed (d-major)
    float* Kt = Qt + 64 * 128;         // [64][68]   K transposed (d-major), padded
    float* Vs = Kt + 64 * 68;          // [64][68]   V natural (key-major), padded
    float* Ps = Vs + 64 * 68;          // [128][68]  P (softmaxed scores), padded

    const int tid = threadIdx.x;
    const int tx = tid & 15, ty = tid >> 4;
    const int bh = blockIdx.x;                 // b*H + h
    const int h = bh % H_;
    const int b = bh / H_;
    const int q0 = blockIdx.y * 128;

    const float* qptr = g_q + ((size_t)bh * N_ + q0) * D_;
    const float* kbase = g_k + (size_t)bh * N_ * D_;
    const float* vbase = g_v + (size_t)bh * N_ * D_;
    const float* brow = bias + ((size_t)h * N_ + q0) * N_;

    // load Q tile transposed: Qt[d][r]
    for (int idx = tid; idx < 128 * 16; idx += 256) {
        int r = idx >> 4;
        int dq = idx & 15;
        float4 v = *(const float4*)(qptr + (size_t)r * D_ + dq * 4);
        Qt[(dq * 4 + 0) * 128 + r] = v.x;
        Qt[(dq * 4 + 1) * 128 + r] = v.y;
        Qt[(dq * 4 + 2) * 128 + r] = v.z;
        Qt[(dq * 4 + 3) * 128 + r] = v.w;
    }

    float m_i[8], l_i[8], acc[8][4];
#pragma unroll
    for (int i = 0; i < 8; i++) {
        m_i[i] = -1e30f;
        l_i[i] = 0.f;
#pragma unroll
        for (int j = 0; j < 4; j++) acc[i][j] = 0.f;
    }

    for (int kt = 0; kt < N_; kt += 64) {
        __syncthreads();  // prior PV done reading Kt/Vs/Ps, Q load done (1st iter)
        // load K tile transposed: Kt[d][c]
        for (int idx = tid; idx < 64 * 16; idx += 256) {
            int c = idx >> 4;
            int dq = idx & 15;
            float4 v = *(const float4*)(kbase + (size_t)(kt + c) * D_ + dq * 4);
            Kt[(dq * 4 + 0) * 68 + c] = v.x;
            Kt[(dq * 4 + 1) * 68 + c] = v.y;
            Kt[(dq * 4 + 2) * 68 + c] = v.z;
            Kt[(dq * 4 + 3) * 68 + c] = v.w;
        }
        // load V tile natural: Vs[c][d]
        for (int idx = tid; idx < 64 * 16; idx += 256) {
            int c = idx >> 4;
            int dq = idx & 15;
            float4 v = *(const float4*)(vbase + (size_t)(kt + c) * D_ + dq * 4);
            *(float4*)&Vs[c * 68 + dq * 4] = v;
        }
        __syncthreads();

        // S = Q K^T   (q pre-scaled)
        float s[8][4];
#pragma unroll
        for (int i = 0; i < 8; i++)
#pragma unroll
            for (int j = 0; j < 4; j++) s[i][j] = 0.f;

#pragma unroll 8
        for (int kk = 0; kk < 64; kk++) {
            float a[8], bv[4];
            *(float4*)&a[0] = *(const float4*)&Qt[kk * 128 + ty * 8];
            *(float4*)&a[4] = *(const float4*)&Qt[kk * 128 + ty * 8 + 4];
            *(float4*)&bv[0] = *(const float4*)&Kt[kk * 68 + tx * 4];
#pragma unroll
            for (int i = 0; i < 8; i++)
#pragma unroll
                for (int j = 0; j < 4; j++) s[i][j] += a[i] * bv[j];
        }

        // + rel_pos_bias, online softmax, write P
#pragma unroll
        for (int i = 0; i < 8; i++) {
            float4 bv = *(const float4*)(brow + (size_t)(ty * 8 + i) * N_ + kt + tx * 4);
            s[i][0] += bv.x; s[i][1] += bv.y; s[i][2] += bv.z; s[i][3] += bv.w;

            float mx = fmaxf(fmaxf(s[i][0], s[i][1]), fmaxf(s[i][2], s[i][3]));
#pragma unroll
            for (int off = 1; off < 16; off <<= 1)
                mx = fmaxf(mx, __shfl_xor_sync(0xffffffffu, mx, off));
            float m_new = fmaxf(m_i[i], mx);
            float sf = __expf(m_i[i] - m_new);
            float rs = 0.f;
#pragma unroll
            for (int j = 0; j < 4; j++) {
                s[i][j] = __expf(s[i][j] - m_new);
                rs += s[i][j];
            }
#pragma unroll
            for (int off = 1; off < 16; off <<= 1)
                rs += __shfl_xor_sync(0xffffffffu, rs, off);
            l_i[i] = l_i[i] * sf + rs;
            m_i[i] = m_new;
#pragma unroll
            for (int j = 0; j < 4; j++) acc[i][j] *= sf;
            *(float4*)&Ps[(ty * 8 + i) * 68 + tx * 4] = *(float4*)&s[i][0];
        }
        __syncthreads();

        // O += P V
#pragma unroll 8
        for (int kk = 0; kk < 64; kk++) {
            float vv[4];
            *(float4*)&vv[0] = *(const float4*)&Vs[kk * 68 + tx * 4];
#pragma unroll
            for (int i = 0; i < 8; i++) {
                float p = Ps[(ty * 8 + i) * 68 + kk];
#pragma unroll
                for (int j = 0; j < 4; j++) acc[i][j] += p * vv[j];
            }
        }
    }

    // normalize + store to g_o in [B][N][H*D]
#pragma unroll
    for (int i = 0; i < 8; i++) {
        float inv = 1.f / l_i[i];
        int n = q0 + ty * 8 + i;
        float4 o4;
        o4.x = acc[i][0] * inv;
        o4.y = acc[i][1] * inv;
        o4.z = acc[i][2] * inv;
        o4.w = acc[i][3] * inv;
        *(float4*)(g_o + ((size_t)(b * N_ + n) * C_) + h * D_ + tx * 4) = o4;
    }
}

// ---------------------------------------------------------------------------
// Kernel 3: output projection GEMM: out = g_o @ proj_w^T + proj_b
// Same structure as kernel 1.  Grid (1024/64, 4096/128).
// ---------------------------------------------------------------------------
__global__ __launch_bounds__(256) void proj_gemm_kernel(
    const float* __restrict__ w, const float* __restrict__ pb,
    float* __restrict__ out) {
    __shared__ float As[16][128];
    __shared__ float Bs[16][64];

    const int tid = threadIdx.x;
    const int tx = tid & 15, ty = tid >> 4;
    const int m0 = blockIdx.y * 128;
    const int n0 = blockIdx.x * 64;

    const float* Abase = g_o + (size_t)m0 * C_;
    const float* Bbase = w + (size_t)n0 * C_;

    float acc[8][4];
#pragma unroll
    for (int i = 0; i < 8; i++)
#pragma unroll
        for (int j = 0; j < 4; j++) acc[i][j] = 0.f;

    for (int k0 = 0; k0 < C_; k0 += 16) {
        {
            int idx = tid;
#pragma unroll
            for (int rep = 0; rep < 2; rep++) {
                int row = idx >> 2;
                int kq = idx & 3;
                float4 v = *(const float4*)(Abase + (size_t)row * C_ + k0 + kq * 4);
                As[kq * 4 + 0][row] = v.x;
                As[kq * 4 + 1][row] = v.y;
                As[kq * 4 + 2][row] = v.z;
                As[kq * 4 + 3][row] = v.w;
                idx += 256;
            }
        }
        {
            int n = tid >> 2, kq = tid & 3;
            float4 v = *(const float4*)(Bbase + (size_t)n * C_ + k0 + kq * 4);
            Bs[kq * 4 + 0][n] = v.x;
            Bs[kq * 4 + 1][n] = v.y;
            Bs[kq * 4 + 2][n] = v.z;
            Bs[kq * 4 + 3][n] = v.w;
        }
        __syncthreads();
#pragma unroll
        for (int kk = 0; kk < 16; kk++) {
            float a[8], b[4];
            *(float4*)&a[0] = *(const float4*)&As[kk][ty * 8];
            *(float4*)&a[4] = *(const float4*)&As[kk][ty * 8 + 4];
            *(float4*)&b[0] = *(const float4*)&Bs[kk][tx * 4];
#pragma unroll
            for (int i = 0; i < 8; i++)
#pragma unroll
                for (int j = 0; j < 4; j++) acc[i][j] += a[i] * b[j];
        }
        __syncthreads();
    }

#pragma unroll
    for (int i = 0; i < 8; i++) {
        const int m = m0 + ty * 8 + i;
        const int n = n0 + tx * 4;
        float4 o4;
        o4.x = acc[i][0] + pb[n + 0];
        o4.y = acc[i][1] + pb[n + 1];
        o4.z = acc[i][2] + pb[n + 2];
        o4.w = acc[i][3] + pb[n + 3];
        *(float4*)(out + (size_t)m * C_ + n) = o4;
    }
}

// ---------------------------------------------------------------------------
extern "C" void kernel_launch(void* const* d_in, const int* in_sizes, int n_in,
                              void* d_out, int out_size) {
    const float* x      = (const float*)d_in[0];   // [B,N,C]
    const float* bias   = (const float*)d_in[1];   // [H,N,N]
    const float* qkv_w  = (const float*)d_in[2];   // [3C,C]
    const float* q_bias = (const float*)d_in[3];   // [C]
    const float* v_bias = (const float*)d_in[4];   // [C]
    const float* proj_w = (const float*)d_in[5];   // [C,C]
    const float* proj_b = (const float*)d_in[6];   // [C]
    float* out = (float*)d_out;                    // [B,N,C]

    const int attn_smem = 102400;  // 100 KB dynamic
    cudaFuncSetAttribute(attn_kernel, cudaFuncAttributeMaxDynamicSharedMemorySize,
                         attn_smem);

    qkv_gemm_kernel<<<dim3(3 * C_ / 64, B_ * N_ / 128), 256>>>(x, qkv_w, q_bias, v_bias);
    attn_kernel<<<dim3(B_ * H_, N_ / 128), 256, attn_smem>>>(bias);
    proj_gemm_kernel<<<dim3(C_ / 64, B_ * N_ / 128), 256>>>(proj_w, proj_b, out);
}

// round 4
// speedup vs baseline: 2.7820x; 2.7763x over previous
#include <cuda_runtime.h>
#include <cuda_bf16.h>
#include <cstdint>
#include <cstddef>

#define B_ 2
#define N_ 2048
#define C_ 1024
#define H_ 16
#define D_ 64
#define SCALE_ 0.125f
#define NKV (B_*H_*N_*D_)

// bf16-split scratch (hi/lo), attention fp32 output
__device__ __nv_bfloat16 g_qh[NKV], g_ql[NKV];
__device__ __nv_bfloat16 g_kh[NKV], g_kl[NKV];
__device__ __nv_bfloat16 g_vh[NKV], g_vl[NKV];
__device__ float g_o[(size_t)B_ * N_ * C_];

// ---------------- helpers ----------------
__device__ __forceinline__ uint32_t pk2(__nv_bfloat16 a, __nv_bfloat16 b) {
    return (uint32_t)__bfloat16_as_ushort(a) | ((uint32_t)__bfloat16_as_ushort(b) << 16);
}
__device__ __forceinline__ void split2(float x, float y, uint32_t& h, uint32_t& l) {
    __nv_bfloat16 hx = __float2bfloat16_rn(x), hy = __float2bfloat16_rn(y);
    h = pk2(hx, hy);
    l = pk2(__float2bfloat16_rn(x - __bfloat162float(hx)),
            __float2bfloat16_rn(y - __bfloat162float(hy)));
}
__device__ __forceinline__ void ldsm4(uint32_t (&r)[4], uint32_t a) {
    asm volatile("ldmatrix.sync.aligned.m8n8.x4.shared.b16 {%0,%1,%2,%3}, [%4];\n"
                 : "=r"(r[0]), "=r"(r[1]), "=r"(r[2]), "=r"(r[3]) : "r"(a));
}
__device__ __forceinline__ void ldsm4t(uint32_t (&r)[4], uint32_t a) {
    asm volatile("ldmatrix.sync.aligned.m8n8.x4.trans.shared.b16 {%0,%1,%2,%3}, [%4];\n"
                 : "=r"(r[0]), "=r"(r[1]), "=r"(r[2]), "=r"(r[3]) : "r"(a));
}
__device__ __forceinline__ void mma16816(float (&c)[4], const uint32_t (&a)[4],
                                         uint32_t b0, uint32_t b1) {
    asm volatile(
        "mma.sync.aligned.m16n8k16.row.col.f32.bf16.bf16.f32 "
        "{%0,%1,%2,%3}, {%4,%5,%6,%7}, {%8,%9}, {%0,%1,%2,%3};\n"
        : "+f"(c[0]), "+f"(c[1]), "+f"(c[2]), "+f"(c[3])
        : "r"(a[0]), "r"(a[1]), "r"(a[2]), "r"(a[3]), "r"(b0), "r"(b1));
}
__device__ __forceinline__ void mma16816p(float (&c)[4], const uint32_t* a,
                                          uint32_t b0, uint32_t b1) {
    asm volatile(
        "mma.sync.aligned.m16n8k16.row.col.f32.bf16.bf16.f32 "
        "{%0,%1,%2,%3}, {%4,%5,%6,%7}, {%8,%9}, {%0,%1,%2,%3};\n"
        : "+f"(c[0]), "+f"(c[1]), "+f"(c[2]), "+f"(c[3])
        : "r"(a[0]), "r"(a[1]), "r"(a[2]), "r"(a[3]), "r"(b0), "r"(b1));
}
__device__ __forceinline__ void cp16(uint32_t dst, const void* src) {
    asm volatile("cp.async.cg.shared.global [%0], [%1], 16;\n" ::"r"(dst), "l"(src));
}

// ---------------------------------------------------------------------------
// Shared MMA GEMM: Out[M,Ncols] = A[M,1024] @ W[Ncols,1024]^T (+epilogue)
// MODE 0: qkv (A = x param; bias qb/vb, scale, split-write to q/k/v scratch)
// MODE 1: proj (A = g_o device global read IN DEVICE CODE; bias qb, fp32 out)
// BM=BN=128, BK=32, 256 thr; warp tile 64(m) x 32(n); 3-MMA bf16 split.
// ---------------------------------------------------------------------------
template <int MODE>
__global__ __launch_bounds__(256, 1) void gemm_kernel(
    const float* __restrict__ A, const float* __restrict__ W,
    const float* __restrict__ qb, const float* __restrict__ vb,
    float* __restrict__ out) {
    __shared__ __align__(16) __nv_bfloat16 sAh[128 * 40], sAl[128 * 40];
    __shared__ __align__(16) __nv_bfloat16 sBh[128 * 40], sBl[128 * 40];
    const int tid = threadIdx.x, lane = tid & 31, wid = tid >> 5;
    const int wm = wid & 1, wn = wid >> 1;
    const int m0 = blockIdx.y * 128, n0 = blockIdx.x * 128;
    // MODE 1 must take g_o's address in DEVICE code (host shadow is a trap).
    const float* Abase = (MODE == 1) ? (const float*)g_o : A;
    const float* Ab = Abase + (size_t)m0 * C_;
    const float* Bb = W + (size_t)n0 * C_;
    const int lrow = tid >> 3, lkq = tid & 7;

    float c[4][4][4] = {};
    float4 rA[4], rB[4];

    auto ldg = [&](int k0) {
#pragma unroll
        for (int t = 0; t < 4; t++) {
            rA[t] = *(const float4*)(Ab + (size_t)(lrow + t * 32) * C_ + k0 + lkq * 4);
            rB[t] = *(const float4*)(Bb + (size_t)(lrow + t * 32) * C_ + k0 + lkq * 4);
        }
    };
    auto sts = [&]() {
#pragma unroll
        for (int t = 0; t < 4; t++) {
            uint32_t h0, l0, h1, l1;
            int o = (lrow + t * 32) * 40 + lkq * 4;
            split2(rA[t].x, rA[t].y, h0, l0);
            split2(rA[t].z, rA[t].w, h1, l1);
            *(uint2*)&sAh[o] = make_uint2(h0, h1);
            *(uint2*)&sAl[o] = make_uint2(l0, l1);
            split2(rB[t].x, rB[t].y, h0, l0);
            split2(rB[t].z, rB[t].w, h1, l1);
            *(uint2*)&sBh[o] = make_uint2(h0, h1);
            *(uint2*)&sBl[o] = make_uint2(l0, l1);
        }
    };

    ldg(0);
    sts();
    __syncthreads();

    const uint32_t bAh = (uint32_t)__cvta_generic_to_shared(sAh);
    const uint32_t bAl = (uint32_t)__cvta_generic_to_shared(sAl);
    const uint32_t bBh = (uint32_t)__cvta_generic_to_shared(sBh);
    const uint32_t bBl = (uint32_t)__cvta_generic_to_shared(sBl);
    const int arow = wm * 64 + (lane & 15);
    const int acol = (lane >> 4) << 3;
    const int brow = wn * 32 + (lane & 7) + ((lane >> 4) << 3);
    const int bcol = ((lane >> 3) & 1) << 3;

    for (int k0 = 0; k0 < C_; k0 += 32) {
        const bool more = (k0 + 32 < C_);
        if (more) ldg(k0 + 32);
#pragma unroll
        for (int s = 0; s < 2; s++) {
            uint32_t ah[4][4], al[4][4], bh[2][4], bl[2][4];
#pragma unroll
            for (int i = 0; i < 4; i++) {
                uint32_t off = (uint32_t)(((arow + i * 16) * 40 + s * 16 + acol) * 2);
                ldsm4(ah[i], bAh + off);
                ldsm4(al[i], bAl + off);
            }
#pragma unroll
            for (int jp = 0; jp < 2; jp++) {
                uint32_t off = (uint32_t)(((brow + jp * 16) * 40 + s * 16 + bcol) * 2);
                ldsm4(bh[jp], bBh + off);
                ldsm4(bl[jp], bBl + off);
            }
#pragma unroll
            for (int i = 0; i < 4; i++)
#pragma unroll
                for (int j = 0; j < 4; j++) {
                    int jp = j >> 1, o2 = (j & 1) * 2;
                    mma16816(c[i][j], ah[i], bh[jp][o2], bh[jp][o2 + 1]);
                    mma16816(c[i][j], al[i], bh[jp][o2], bh[jp][o2 + 1]);
                    mma16816(c[i][j], ah[i], bl[jp][o2], bl[jp][o2 + 1]);
                }
        }
        if (more) {
            __syncthreads();
            sts();
            __syncthreads();
        }
    }

    // epilogue
#pragma unroll
    for (int i = 0; i < 4; i++) {
#pragma unroll
        for (int rr = 0; rr < 2; rr++) {
            const int m = m0 + wm * 64 + i * 16 + (lane >> 2) + rr * 8;
#pragma unroll
            for (int j = 0; j < 4; j++) {
                const int col = n0 + wn * 32 + j * 8 + 2 * (lane & 3);
                float v0 = c[i][j][rr * 2 + 0], v1 = c[i][j][rr * 2 + 1];
                if (MODE == 1) {
                    *(float2*)(out + (size_t)m * C_ + col) =
                        make_float2(v0 + qb[col], v1 + qb[col + 1]);
                } else {
                    const int which = col >> 10, ch = col & 1023;
                    const int hh = ch >> 6, d = ch & 63;
                    if (which == 0) {
                        v0 = (v0 + qb[ch]) * SCALE_;
                        v1 = (v1 + qb[ch + 1]) * SCALE_;
                    } else if (which == 2) {
                        v0 += vb[ch];
                        v1 += vb[ch + 1];
                    }
                    uint32_t h, l;
                    split2(v0, v1, h, l);
                    const int bb = m >> 11, nn = m & (N_ - 1);
                    size_t off = ((size_t)(bb * H_ + hh) * N_ + nn) * D_ + d;
                    __nv_bfloat16 *dh = (which == 0) ? g_qh : (which == 1 ? g_kh : g_vh);
                    __nv_bfloat16 *dl = (which == 0) ? g_ql : (which == 1 ? g_kl : g_vl);
                    *(uint32_t*)(dh + off) = h;
                    *(uint32_t*)(dl + off) = l;
                }
            }
        }
    }
}

// ---------------------------------------------------------------------------
// Fused flash attention, bf16-split MMA. Grid (B*H, N/128), 256 thr / 8 warps.
// Warp = 16 q-rows. Key tiles of 64, cp.async double-buffered K/V (hi/lo).
// smem: Qh,Ql[128x72] + 2 bufs x (Kh,Kl,Vh,Vl)[64x72] = 108KB.
// ---------------------------------------------------------------------------
#define KVB 4608  // 64*72 elements
__global__ __launch_bounds__(256, 1) void attn_kernel(const float* __restrict__ bias) {
    extern __shared__ __nv_bfloat16 sm[];
    const uint32_t sb = (uint32_t)__cvta_generic_to_shared(sm);
    const int tid = threadIdx.x, lane = tid & 31, wid = tid >> 5;
    const int bh = blockIdx.x, hh = bh & (H_ - 1), bb = bh >> 4;
    const int q0 = blockIdx.y * 128, wrow = wid * 16;

    const __nv_bfloat16* qhp = g_qh + ((size_t)bh * N_ + q0) * D_;
    const __nv_bfloat16* qlp = g_ql + ((size_t)bh * N_ + q0) * D_;
    const __nv_bfloat16* khp = g_kh + (size_t)bh * N_ * D_;
    const __nv_bfloat16* klp = g_kl + (size_t)bh * N_ * D_;
    const __nv_bfloat16* vhp = g_vh + (size_t)bh * N_ * D_;
    const __nv_bfloat16* vlp = g_vl + (size_t)bh * N_ * D_;
    const float* bp0 =
        bias + ((size_t)hh * N_ + q0 + wrow + (lane >> 2)) * N_ + 2 * (lane & 3);
    const float* bp1 = bp0 + 8 * N_;

    // Q tile into smem (hi at elem 0, lo at elem 9216)
#pragma unroll
    for (int t = 0; t < 8; t++) {
        int idx = tid + t * 256, row = idx >> 4, seg = idx & 15;
        *(uint2*)&sm[row * 72 + seg * 4] = *(const uint2*)(qhp + row * D_ + seg * 4);
        *(uint2*)&sm[9216 + row * 72 + seg * 4] = *(const uint2*)(qlp + row * D_ + seg * 4);
    }

#define ISSUE_KV(KT, BUF)                                                        \
    {                                                                            \
        _Pragma("unroll") for (int t = 0; t < 2; t++) {                          \
            int chn = tid + t * 256, row = chn >> 3, seg = chn & 7;              \
            uint32_t doff = sb + (18432 + (BUF)*18432 + row * 72 + seg * 8) * 2; \
            size_t soff = (size_t)((KT) + row) * D_ + seg * 8;                   \
            cp16(doff, khp + soff);                                              \
            cp16(doff + KVB * 2, klp + soff);                                    \
            cp16(doff + 2 * KVB * 2, vhp + soff);                                \
            cp16(doff + 3 * KVB * 2, vlp + soff);                                \
        }                                                                        \
        asm volatile("cp.async.commit_group;\n");                                \
    }

    ISSUE_KV(0, 0);
    __syncthreads();

    // persistent Q fragments
    uint32_t qh[4][4], ql[4][4];
    {
        const uint32_t aq = sb + ((wrow + (lane & 15)) * 72 + ((lane >> 4) << 3)) * 2;
#pragma unroll
        for (int kc = 0; kc < 4; kc++) {
            ldsm4(qh[kc], aq + kc * 32);
            ldsm4(ql[kc], aq + 9216 * 2 + kc * 32);
        }
    }

    float m0 = -1e30f, m1 = -1e30f, l0 = 0.f, l1 = 0.f;
    float o[8][4] = {};
    const int krow = (lane & 7) + ((lane >> 4) << 3);
    const int kcol = ((lane >> 3) & 1) << 3;
    const int vrow = (lane & 7) + (((lane >> 3) & 1) << 3);
    const int vcol = (lane >> 4) << 3;

    for (int t = 0; t < N_ / 64; t++) {
        const int kt = t * 64, buf = t & 1;
        __syncthreads();  // all warps done reading buf^1 from iter t-1
        if (t + 1 < N_ / 64) {
            ISSUE_KV(kt + 64, buf ^ 1);
            asm volatile("cp.async.wait_group 1;\n");
        } else {
            asm volatile("cp.async.wait_group 0;\n");
        }
        __syncthreads();
        const uint32_t kvb = sb + (18432 + buf * 18432) * 2;

        // ---- S = Q K^T (3-MMA split) ----
        float s[8][4] = {};
#pragma unroll
        for (int kc = 0; kc < 4; kc++)
#pragma unroll
            for (int g = 0; g < 4; g++) {
                uint32_t kh[4], kl[4];
                uint32_t ka = kvb + (uint32_t)(((g * 16 + krow) * 72 + kc * 16 + kcol) * 2);
                ldsm4(kh, ka);
                ldsm4(kl, ka + KVB * 2);
                mma16816(s[2 * g], qh[kc], kh[0], kh[1]);
                mma16816(s[2 * g + 1], qh[kc], kh[2], kh[3]);
                mma16816(s[2 * g], ql[kc], kh[0], kh[1]);
                mma16816(s[2 * g + 1], ql[kc], kh[2], kh[3]);
                mma16816(s[2 * g], qh[kc], kl[0], kl[1]);
                mma16816(s[2 * g + 1], qh[kc], kl[2], kl[3]);
            }

        // ---- bias + online softmax ----
        float mx0 = -1e30f, mx1 = -1e30f;
#pragma unroll
        for (int j = 0; j < 8; j++) {
            float2 ba = *(const float2*)(bp0 + kt + j * 8);
            float2 bc = *(const float2*)(bp1 + kt + j * 8);
            s[j][0] += ba.x; s[j][1] += ba.y;
            s[j][2] += bc.x; s[j][3] += bc.y;
            mx0 = fmaxf(mx0, fmaxf(s[j][0], s[j][1]));
            mx1 = fmaxf(mx1, fmaxf(s[j][2], s[j][3]));
        }
        mx0 = fmaxf(mx0, __shfl_xor_sync(~0u, mx0, 1));
        mx0 = fmaxf(mx0, __shfl_xor_sync(~0u, mx0, 2));
        mx1 = fmaxf(mx1, __shfl_xor_sync(~0u, mx1, 1));
        mx1 = fmaxf(mx1, __shfl_xor_sync(~0u, mx1, 2));
        float mn0 = fmaxf(m0, mx0), mn1 = fmaxf(m1, mx1);
        float sf0 = __expf(m0 - mn0), sf1 = __expf(m1 - mn1);
        float rs0 = 0.f, rs1 = 0.f;
#pragma unroll
        for (int j = 0; j < 8; j++) {
            s[j][0] = __expf(s[j][0] - mn0);
            s[j][1] = __expf(s[j][1] - mn0);
            s[j][2] = __expf(s[j][2] - mn1);
            s[j][3] = __expf(s[j][3] - mn1);
            rs0 += s[j][0] + s[j][1];
            rs1 += s[j][2] + s[j][3];
        }
        rs0 += __shfl_xor_sync(~0u, rs0, 1);
        rs0 += __shfl_xor_sync(~0u, rs0, 2);
        rs1 += __shfl_xor_sync(~0u, rs1, 1);
        rs1 += __shfl_xor_sync(~0u, rs1, 2);
        l0 = l0 * sf0 + rs0;
        l1 = l1 * sf1 + rs1;
        m0 = mn0;
        m1 = mn1;
#pragma unroll
        for (int j = 0; j < 8; j++) {
            o[j][0] *= sf0; o[j][1] *= sf0;
            o[j][2] *= sf1; o[j][3] *= sf1;
        }

        // ---- O += P V (P split in registers, V via ldmatrix.trans) ----
#pragma unroll
        for (int tc = 0; tc < 4; tc++) {
            uint32_t ph[4], pl[4];
            split2(s[2 * tc][0], s[2 * tc][1], ph[0], pl[0]);
            split2(s[2 * tc][2], s[2 * tc][3], ph[1], pl[1]);
            split2(s[2 * tc + 1][0], s[2 * tc + 1][1], ph[2], pl[2]);
            split2(s[2 * tc + 1][2], s[2 * tc + 1][3], ph[3], pl[3]);
#pragma unroll
            for (int dg = 0; dg < 4; dg++) {
                uint32_t vh[4], vl[4];
                uint32_t va = kvb + 2 * KVB * 2 +
                              (uint32_t)(((tc * 16 + vrow) * 72 + dg * 16 + vcol) * 2);
                ldsm4t(vh, va);
                ldsm4t(vl, va + KVB * 2);
                mma16816p(o[2 * dg], ph, vh[0], vh[1]);
                mma16816p(o[2 * dg + 1], ph, vh[2], vh[3]);
                mma16816p(o[2 * dg], pl, vh[0], vh[1]);
                mma16816p(o[2 * dg + 1], pl, vh[2], vh[3]);
                mma16816p(o[2 * dg], ph, vl[0], vl[1]);
                mma16816p(o[2 * dg + 1], ph, vl[2], vl[3]);
            }
        }
    }

    // normalize + store fp32 to g_o [B,N,H*D]
    const float inv0 = 1.f / l0, inv1 = 1.f / l1;
    const int nrow = q0 + wrow + (lane >> 2);
    float* or0 = g_o + (size_t)(bb * N_ + nrow) * C_ + hh * D_;
    float* or1 = or0 + 8 * C_;
#pragma unroll
    for (int j = 0; j < 8; j++) {
        const int d = j * 8 + 2 * (lane & 3);
        *(float2*)(or0 + d) = make_float2(o[j][0] * inv0, o[j][1] * inv0);
        *(float2*)(or1 + d) = make_float2(o[j][2] * inv1, o[j][3] * inv1);
    }
}

// ---------------------------------------------------------------------------
extern "C" void kernel_launch(void* const* d_in, const int* in_sizes, int n_in,
                              void* d_out, int out_size) {
    const float* x      = (const float*)d_in[0];
    const float* bias   = (const float*)d_in[1];
    const float* qkv_w  = (const float*)d_in[2];
    const float* q_bias = (const float*)d_in[3];
    const float* v_bias = (const float*)d_in[4];
    const float* proj_w = (const float*)d_in[5];
    const float* proj_b = (const float*)d_in[6];
    float* out = (float*)d_out;

    // unconditional: cheap, deterministic, capture-legal (not a stream op)
    cudaFuncSetAttribute(attn_kernel, cudaFuncAttributeMaxDynamicSharedMemorySize,
                         110592);

    gemm_kernel<0><<<dim3(24, 32), 256>>>(x, qkv_w, q_bias, v_bias, nullptr);
    attn_kernel<<<dim3(B_ * H_, N_ / 128), 256, 110592>>>(bias);
    gemm_kernel<1><<<dim3(8, 32), 256>>>(nullptr, proj_w, proj_b, nullptr, out);
}

// round 5
// speedup vs baseline: 2.9236x; 1.0509x over previous
#include <cuda_runtime.h>
#include <cuda_bf16.h>
#include <cstdint>
#include <cstddef>

#define B_ 2
#define N_ 2048
#define C_ 1024
#define H_ 16
#define D_ 64
#define SCALE_ 0.125f
#define NKV (B_*H_*N_*D_)

// pre-split bf16 scratch (hi/lo)
__device__ __nv_bfloat16 g_xh[(size_t)B_*N_*C_],  g_xl[(size_t)B_*N_*C_];   // x
__device__ __nv_bfloat16 g_wh[(size_t)3*C_*C_],   g_wl[(size_t)3*C_*C_];    // qkv_w
__device__ __nv_bfloat16 g_pwh[(size_t)C_*C_],    g_pwl[(size_t)C_*C_];     // proj_w
__device__ __nv_bfloat16 g_qh[NKV], g_ql[NKV];
__device__ __nv_bfloat16 g_kh[NKV], g_kl[NKV];
__device__ __nv_bfloat16 g_vh[NKV], g_vl[NKV];
__device__ __nv_bfloat16 g_oh[(size_t)B_*N_*C_],  g_ol[(size_t)B_*N_*C_];   // attn out

// ---------------- helpers ----------------
__device__ __forceinline__ uint32_t pk2(__nv_bfloat16 a, __nv_bfloat16 b) {
    return (uint32_t)__bfloat16_as_ushort(a) | ((uint32_t)__bfloat16_as_ushort(b) << 16);
}
__device__ __forceinline__ void split2(float x, float y, uint32_t& h, uint32_t& l) {
    __nv_bfloat16 hx = __float2bfloat16_rn(x), hy = __float2bfloat16_rn(y);
    h = pk2(hx, hy);
    l = pk2(__float2bfloat16_rn(x - __bfloat162float(hx)),
            __float2bfloat16_rn(y - __bfloat162float(hy)));
}
__device__ __forceinline__ void ldsm4(uint32_t (&r)[4], uint32_t a) {
    asm volatile("ldmatrix.sync.aligned.m8n8.x4.shared.b16 {%0,%1,%2,%3}, [%4];\n"
                 : "=r"(r[0]), "=r"(r[1]), "=r"(r[2]), "=r"(r[3]) : "r"(a));
}
__device__ __forceinline__ void ldsm4t(uint32_t (&r)[4], uint32_t a) {
    asm volatile("ldmatrix.sync.aligned.m8n8.x4.trans.shared.b16 {%0,%1,%2,%3}, [%4];\n"
                 : "=r"(r[0]), "=r"(r[1]), "=r"(r[2]), "=r"(r[3]) : "r"(a));
}
__device__ __forceinline__ void mma16816(float (&c)[4], const uint32_t (&a)[4],
                                         uint32_t b0, uint32_t b1) {
    asm volatile(
        "mma.sync.aligned.m16n8k16.row.col.f32.bf16.bf16.f32 "
        "{%0,%1,%2,%3}, {%4,%5,%6,%7}, {%8,%9}, {%0,%1,%2,%3};\n"
        : "+f"(c[0]), "+f"(c[1]), "+f"(c[2]), "+f"(c[3])
        : "r"(a[0]), "r"(a[1]), "r"(a[2]), "r"(a[3]), "r"(b0), "r"(b1));
}
__device__ __forceinline__ void mma16816p(float (&c)[4], const uint32_t* a,
                                          uint32_t b0, uint32_t b1) {
    asm volatile(
        "mma.sync.aligned.m16n8k16.row.col.f32.bf16.bf16.f32 "
        "{%0,%1,%2,%3}, {%4,%5,%6,%7}, {%8,%9}, {%0,%1,%2,%3};\n"
        : "+f"(c[0]), "+f"(c[1]), "+f"(c[2]), "+f"(c[3])
        : "r"(a[0]), "r"(a[1]), "r"(a[2]), "r"(a[3]), "r"(b0), "r"(b1));
}
__device__ __forceinline__ void cp16(uint32_t dst, const void* src) {
    asm volatile("cp.async.cg.shared.global [%0], [%1], 16;\n" ::"r"(dst), "l"(src));
}

// ---------------------------------------------------------------------------
// Split pass: fp32 -> (hi, lo) bf16. Memory bound, ~32MB total.
// ---------------------------------------------------------------------------
__global__ __launch_bounds__(256) void split_kernel(const float4* __restrict__ src,
                                                    uint2* __restrict__ dh,
                                                    uint2* __restrict__ dl, int n4) {
    int i = blockIdx.x * 256 + threadIdx.x;
    if (i < n4) {
        float4 v = src[i];
        uint32_t h0, l0, h1, l1;
        split2(v.x, v.y, h0, l0);
        split2(v.z, v.w, h1, l1);
        dh[i] = make_uint2(h0, h1);
        dl[i] = make_uint2(l0, l1);
    }
}

// ---------------------------------------------------------------------------
// Pre-split GEMM: Out[M,Nc] = A @ W^T, A/W hi/lo bf16 in __device__ globals.
// MODE 0: A=x-split, W=qkv_w-split; epilogue bias/scale + split-write q/k/v.
// MODE 1: A=o-split, W=proj_w-split; epilogue +proj_b, fp32 out.
// BM=BN=128, BK=32, 256 thr, warp 64x32; cp.async double-buffered mainloop.
// smem: 2 stages x 4 arrays x 128x40 bf16 = 80KB dynamic.
// ---------------------------------------------------------------------------
template <int MODE>
__global__ __launch_bounds__(256, 1) void gemm2_kernel(
    const float* __restrict__ qb, const float* __restrict__ vb,
    float* __restrict__ out) {
    extern __shared__ __nv_bfloat16 gsm[];
    const uint32_t sb = (uint32_t)__cvta_generic_to_shared(gsm);
    const int tid = threadIdx.x, lane = tid & 31, wid = tid >> 5;
    const int wm = wid & 1, wn = wid >> 1;
    const int m0 = blockIdx.y * 128, n0 = blockIdx.x * 128;

    const __nv_bfloat16* Ah = (MODE == 1) ? g_oh : g_xh;
    const __nv_bfloat16* Al = (MODE == 1) ? g_ol : g_xl;
    const __nv_bfloat16* Bh = (MODE == 1) ? g_pwh : g_wh;
    const __nv_bfloat16* Bl = (MODE == 1) ? g_pwl : g_wl;

    // stage layout (elements): stage*20480 + {Ah:0, Al:5120, Bh:10240, Bl:15360}
    auto issue = [&](int ko, int st) {
        uint32_t base = sb + (uint32_t)st * (20480 * 2);
#pragma unroll
        for (int t = 0; t < 2; t++) {
            int chn = tid + t * 256;
            int row = chn >> 2, seg = chn & 3;
            uint32_t doff = (uint32_t)(row * 40 + seg * 8) * 2;
            size_t aoff = (size_t)(m0 + row) * C_ + ko + seg * 8;
            size_t boff = (size_t)(n0 + row) * C_ + ko + seg * 8;
            cp16(base + doff, Ah + aoff);
            cp16(base + 5120 * 2 + doff, Al + aoff);
            cp16(base + 10240 * 2 + doff, Bh + boff);
            cp16(base + 15360 * 2 + doff, Bl + boff);
        }
        asm volatile("cp.async.commit_group;\n");
    };

    float c[4][4][4] = {};
    const int arow = wm * 64 + (lane & 15);
    const int acol = (lane >> 4) << 3;
    const int brow = wn * 32 + (lane & 7) + ((lane >> 4) << 3);
    const int bcol = ((lane >> 3) & 1) << 3;

    issue(0, 0);

    for (int i = 0; i < 32; i++) {
        const int buf = i & 1;
        __syncthreads();  // all warps done reading buf^1 (iter i-1)
        if (i + 1 < 32) {
            issue((i + 1) * 32, buf ^ 1);
            asm volatile("cp.async.wait_group 1;\n");
        } else {
            asm volatile("cp.async.wait_group 0;\n");
        }
        __syncthreads();
        const uint32_t base = sb + (uint32_t)buf * (20480 * 2);

#pragma unroll
        for (int s = 0; s < 2; s++) {
            uint32_t ah[4][4], al[4][4], bh[2][4], bl[2][4];
#pragma unroll
            for (int ii = 0; ii < 4; ii++) {
                uint32_t off = (uint32_t)(((arow + ii * 16) * 40 + s * 16 + acol) * 2);
                ldsm4(ah[ii], base + off);
                ldsm4(al[ii], base + 5120 * 2 + off);
            }
#pragma unroll
            for (int jp = 0; jp < 2; jp++) {
                uint32_t off = (uint32_t)(((brow + jp * 16) * 40 + s * 16 + bcol) * 2);
                ldsm4(bh[jp], base + 10240 * 2 + off);
                ldsm4(bl[jp], base + 15360 * 2 + off);
            }
#pragma unroll
            for (int ii = 0; ii < 4; ii++)
#pragma unroll
                for (int j = 0; j < 4; j++) {
                    int jp = j >> 1, o2 = (j & 1) * 2;
                    mma16816(c[ii][j], ah[ii], bh[jp][o2], bh[jp][o2 + 1]);
                    mma16816(c[ii][j], al[ii], bh[jp][o2], bh[jp][o2 + 1]);
                    mma16816(c[ii][j], ah[ii], bl[jp][o2], bl[jp][o2 + 1]);
                }
        }
    }

    // epilogue
#pragma unroll
    for (int i = 0; i < 4; i++) {
#pragma unroll
        for (int rr = 0; rr < 2; rr++) {
            const int m = m0 + wm * 64 + i * 16 + (lane >> 2) + rr * 8;
#pragma unroll
            for (int j = 0; j < 4; j++) {
                const int col = n0 + wn * 32 + j * 8 + 2 * (lane & 3);
                float v0 = c[i][j][rr * 2 + 0], v1 = c[i][j][rr * 2 + 1];
                if (MODE == 1) {
                    *(float2*)(out + (size_t)m * C_ + col) =
                        make_float2(v0 + qb[col], v1 + qb[col + 1]);
                } else {
                    const int which = col >> 10, ch = col & 1023;
                    const int hh = ch >> 6, d = ch & 63;
                    if (which == 0) {
                        v0 = (v0 + qb[ch]) * SCALE_;
                        v1 = (v1 + qb[ch + 1]) * SCALE_;
                    } else if (which == 2) {
                        v0 += vb[ch];
                        v1 += vb[ch + 1];
                    }
                    uint32_t h, l;
                    split2(v0, v1, h, l);
                    const int bb = m >> 11, nn = m & (N_ - 1);
                    size_t off = ((size_t)(bb * H_ + hh) * N_ + nn) * D_ + d;
                    __nv_bfloat16 *dh = (which == 0) ? g_qh : (which == 1 ? g_kh : g_vh);
                    __nv_bfloat16 *dl = (which == 0) ? g_ql : (which == 1 ? g_kl : g_vl);
                    *(uint32_t*)(dh + off) = h;
                    *(uint32_t*)(dl + off) = l;
                }
            }
        }
    }
}

// ---------------------------------------------------------------------------
// Fused flash attention, bf16-split MMA. Grid (B*H, N/128), 256 thr / 8 warps.
// Warp = 16 q-rows; key tiles of 64; cp.async double-buffered K/V (hi/lo).
// Bias tile prefetched to registers before S-MMA. Output written pre-split.
// ---------------------------------------------------------------------------
#define KVB 4608  // 64*72 elements
__global__ __launch_bounds__(256, 1) void attn_kernel(const float* __restrict__ bias) {
    extern __shared__ __nv_bfloat16 sm[];
    const uint32_t sb = (uint32_t)__cvta_generic_to_shared(sm);
    const int tid = threadIdx.x, lane = tid & 31, wid = tid >> 5;
    const int bh = blockIdx.x, hh = bh & (H_ - 1), bb = bh >> 4;
    const int q0 = blockIdx.y * 128, wrow = wid * 16;

    const __nv_bfloat16* qhp = g_qh + ((size_t)bh * N_ + q0) * D_;
    const __nv_bfloat16* qlp = g_ql + ((size_t)bh * N_ + q0) * D_;
    const __nv_bfloat16* khp = g_kh + (size_t)bh * N_ * D_;
    const __nv_bfloat16* klp = g_kl + (size_t)bh * N_ * D_;
    const __nv_bfloat16* vhp = g_vh + (size_t)bh * N_ * D_;
    const __nv_bfloat16* vlp = g_vl + (size_t)bh * N_ * D_;
    const float* bp0 =
        bias + ((size_t)hh * N_ + q0 + wrow + (lane >> 2)) * N_ + 2 * (lane & 3);
    const float* bp1 = bp0 + 8 * N_;

    // Q tile into smem (hi at elem 0, lo at elem 9216)
#pragma unroll
    for (int t = 0; t < 8; t++) {
        int idx = tid + t * 256, row = idx >> 4, seg = idx & 15;
        *(uint2*)&sm[row * 72 + seg * 4] = *(const uint2*)(qhp + row * D_ + seg * 4);
        *(uint2*)&sm[9216 + row * 72 + seg * 4] = *(const uint2*)(qlp + row * D_ + seg * 4);
    }

#define ISSUE_KV(KT, BUF)                                                        \
    {                                                                            \
        _Pragma("unroll") for (int t = 0; t < 2; t++) {                          \
            int chn = tid + t * 256, row = chn >> 3, seg = chn & 7;              \
            uint32_t doff = sb + (18432 + (BUF)*18432 + row * 72 + seg * 8) * 2; \
            size_t soff = (size_t)((KT) + row) * D_ + seg * 8;                   \
            cp16(doff, khp + soff);                                              \
            cp16(doff + KVB * 2, klp + soff);                                    \
            cp16(doff + 2 * KVB * 2, vhp + soff);                                \
            cp16(doff + 3 * KVB * 2, vlp + soff);                                \
        }                                                                        \
        asm volatile("cp.async.commit_group;\n");                                \
    }

    ISSUE_KV(0, 0);
    __syncthreads();

    // persistent Q fragments
    uint32_t qh[4][4], ql[4][4];
    {
        const uint32_t aq = sb + ((wrow + (lane & 15)) * 72 + ((lane >> 4) << 3)) * 2;
#pragma unroll
        for (int kc = 0; kc < 4; kc++) {
            ldsm4(qh[kc], aq + kc * 32);
            ldsm4(ql[kc], aq + 9216 * 2 + kc * 32);
        }
    }

    float m0 = -1e30f, m1 = -1e30f, l0 = 0.f, l1 = 0.f;
    float o[8][4] = {};
    const int krow = (lane & 7) + ((lane >> 4) << 3);
    const int kcol = ((lane >> 3) & 1) << 3;
    const int vrow = (lane & 7) + (((lane >> 3) & 1) << 3);
    const int vcol = (lane >> 4) << 3;

    for (int t = 0; t < N_ / 64; t++) {
        const int kt = t * 64, buf = t & 1;

        // prefetch bias tile into registers (overlaps barrier + S-MMA)
        float2 ba[8], bc[8];
#pragma unroll
        for (int j = 0; j < 8; j++) {
            ba[j] = *(const float2*)(bp0 + kt + j * 8);
            bc[j] = *(const float2*)(bp1 + kt + j * 8);
        }

        __syncthreads();  // all warps done reading buf^1 from iter t-1
        if (t + 1 < N_ / 64) {
            ISSUE_KV(kt + 64, buf ^ 1);
            asm volatile("cp.async.wait_group 1;\n");
        } else {
            asm volatile("cp.async.wait_group 0;\n");
        }
        __syncthreads();
        const uint32_t kvb = sb + (18432 + buf * 18432) * 2;

        // ---- S = Q K^T (3-MMA split) ----
        float s[8][4] = {};
#pragma unroll
        for (int kc = 0; kc < 4; kc++)
#pragma unroll
            for (int g = 0; g < 4; g++) {
                uint32_t kh[4], kl[4];
                uint32_t ka = kvb + (uint32_t)(((g * 16 + krow) * 72 + kc * 16 + kcol) * 2);
                ldsm4(kh, ka);
                ldsm4(kl, ka + KVB * 2);
                mma16816(s[2 * g], qh[kc], kh[0], kh[1]);
                mma16816(s[2 * g + 1], qh[kc], kh[2], kh[3]);
                mma16816(s[2 * g], ql[kc], kh[0], kh[1]);
                mma16816(s[2 * g + 1], ql[kc], kh[2], kh[3]);
                mma16816(s[2 * g], qh[kc], kl[0], kl[1]);
                mma16816(s[2 * g + 1], qh[kc], kl[2], kl[3]);
            }

        // ---- bias + online softmax ----
        float mx0 = -1e30f, mx1 = -1e30f;
#pragma unroll
        for (int j = 0; j < 8; j++) {
            s[j][0] += ba[j].x; s[j][1] += ba[j].y;
            s[j][2] += bc[j].x; s[j][3] += bc[j].y;
            mx0 = fmaxf(mx0, fmaxf(s[j][0], s[j][1]));
            mx1 = fmaxf(mx1, fmaxf(s[j][2], s[j][3]));
        }
        mx0 = fmaxf(mx0, __shfl_xor_sync(~0u, mx0, 1));
        mx0 = fmaxf(mx0, __shfl_xor_sync(~0u, mx0, 2));
        mx1 = fmaxf(mx1, __shfl_xor_sync(~0u, mx1, 1));
        mx1 = fmaxf(mx1, __shfl_xor_sync(~0u, mx1, 2));
        float mn0 = fmaxf(m0, mx0), mn1 = fmaxf(m1, mx1);
        float sf0 = __expf(m0 - mn0), sf1 = __expf(m1 - mn1);
        float rs0 = 0.f, rs1 = 0.f;
#pragma unroll
        for (int j = 0; j < 8; j++) {
            s[j][0] = __expf(s[j][0] - mn0);
            s[j][1] = __expf(s[j][1] - mn0);
            s[j][2] = __expf(s[j][2] - mn1);
            s[j][3] = __expf(s[j][3] - mn1);
            rs0 += s[j][0] + s[j][1];
            rs1 += s[j][2] + s[j][3];
        }
        rs0 += __shfl_xor_sync(~0u, rs0, 1);
        rs0 += __shfl_xor_sync(~0u, rs0, 2);
        rs1 += __shfl_xor_sync(~0u, rs1, 1);
        rs1 += __shfl_xor_sync(~0u, rs1, 2);
        l0 = l0 * sf0 + rs0;
        l1 = l1 * sf1 + rs1;
        m0 = mn0;
        m1 = mn1;
#pragma unroll
        for (int j = 0; j < 8; j++) {
            o[j][0] *= sf0; o[j][1] *= sf0;
            o[j][2] *= sf1; o[j][3] *= sf1;
        }

        // ---- O += P V (P split in registers, V via ldmatrix.trans) ----
#pragma unroll
        for (int tc = 0; tc < 4; tc++) {
            uint32_t ph[4], pl[4];
            split2(s[2 * tc][0], s[2 * tc][1], ph[0], pl[0]);
            split2(s[2 * tc][2], s[2 * tc][3], ph[1], pl[1]);
            split2(s[2 * tc + 1][0], s[2 * tc + 1][1], ph[2], pl[2]);
            split2(s[2 * tc + 1][2], s[2 * tc + 1][3], ph[3], pl[3]);
#pragma unroll
            for (int dg = 0; dg < 4; dg++) {
                uint32_t vh[4], vl[4];
                uint32_t va = kvb + 2 * KVB * 2 +
                              (uint32_t)(((tc * 16 + vrow) * 72 + dg * 16 + vcol) * 2);
                ldsm4t(vh, va);
                ldsm4t(vl, va + KVB * 2);
                mma16816p(o[2 * dg], ph, vh[0], vh[1]);
                mma16816p(o[2 * dg + 1], ph, vh[2], vh[3]);
                mma16816p(o[2 * dg], pl, vh[0], vh[1]);
                mma16816p(o[2 * dg + 1], pl, vh[2], vh[3]);
                mma16816p(o[2 * dg], ph, vl[0], vl[1]);
                mma16816p(o[2 * dg + 1], ph, vl[2], vl[3]);
            }
        }
    }

    // normalize + store PRE-SPLIT bf16 to g_oh/g_ol in [B,N,H*D]
    const float inv0 = 1.f / l0, inv1 = 1.f / l1;
    const int nrow = q0 + wrow + (lane >> 2);
    const size_t base0 = (size_t)(bb * N_ + nrow) * C_ + hh * D_;
#pragma unroll
    for (int j = 0; j < 8; j++) {
        const int d = j * 8 + 2 * (lane & 3);
        uint32_t h, l;
        split2(o[j][0] * inv0, o[j][1] * inv0, h, l);
        *(uint32_t*)(g_oh + base0 + d) = h;
        *(uint32_t*)(g_ol + base0 + d) = l;
        split2(o[j][2] * inv1, o[j][3] * inv1, h, l);
        *(uint32_t*)(g_oh + base0 + 8 * C_ + d) = h;
        *(uint32_t*)(g_ol + base0 + 8 * C_ + d) = l;
    }
}

// ---------------------------------------------------------------------------
extern "C" void kernel_launch(void* const* d_in, const int* in_sizes, int n_in,
                              void* d_out, int out_size) {
    const float* x      = (const float*)d_in[0];
    const float* bias   = (const float*)d_in[1];
    const float* qkv_w  = (const float*)d_in[2];
    const float* q_bias = (const float*)d_in[3];
    const float* v_bias = (const float*)d_in[4];
    const float* proj_w = (const float*)d_in[5];
    const float* proj_b = (const float*)d_in[6];
    float* out = (float*)d_out;

    cudaFuncSetAttribute(attn_kernel, cudaFuncAttributeMaxDynamicSharedMemorySize,
                         110592);
    cudaFuncSetAttribute(gemm2_kernel<0>, cudaFuncAttributeMaxDynamicSharedMemorySize,
                         81920);
    cudaFuncSetAttribute(gemm2_kernel<1>, cudaFuncAttributeMaxDynamicSharedMemorySize,
                         81920);

    // device-global destinations must be resolved in device code; split_kernel
    // takes them as params — get device addresses via cudaGetSymbolAddress.
    void *xh, *xl, *wh, *wl, *pwh, *pwl;
    cudaGetSymbolAddress(&xh, g_xh);   cudaGetSymbolAddress(&xl, g_xl);
    cudaGetSymbolAddress(&wh, g_wh);   cudaGetSymbolAddress(&wl, g_wl);
    cudaGetSymbolAddress(&pwh, g_pwh); cudaGetSymbolAddress(&pwl, g_pwl);

    split_kernel<<<(B_*N_*C_/4 + 255)/256, 256>>>((const float4*)x, (uint2*)xh, (uint2*)xl, B_*N_*C_/4);
    split_kernel<<<(3*C_*C_/4 + 255)/256, 256>>>((const float4*)qkv_w, (uint2*)wh, (uint2*)wl, 3*C_*C_/4);
    split_kernel<<<(C_*C_/4 + 255)/256, 256>>>((const float4*)proj_w, (uint2*)pwh, (uint2*)pwl, C_*C_/4);

    gemm2_kernel<0><<<dim3(24, 32), 256, 81920>>>(q_bias, v_bias, nullptr);
    attn_kernel<<<dim3(B_ * H_, N_ / 128), 256, 110592>>>(bias);
    gemm2_kernel<1><<<dim3(8, 32), 256, 81920>>>(proj_b, nullptr, out);
}

// round 7
// speedup vs baseline: 3.0742x; 1.0515x over previous
#include <cuda_runtime.h>
#include <cuda_bf16.h>
#include <cstdint>
#include <cstddef>

#define B_ 2
#define N_ 2048
#define C_ 1024
#define H_ 16
#define D_ 64
#define SCALE_ 0.125f
#define NKV (B_*H_*N_*D_)

// pre-split bf16 scratch (hi/lo)
__device__ __nv_bfloat16 g_xh[(size_t)B_*N_*C_],  g_xl[(size_t)B_*N_*C_];   // x
__device__ __nv_bfloat16 g_wh[(size_t)3*C_*C_],   g_wl[(size_t)3*C_*C_];    // qkv_w
__device__ __nv_bfloat16 g_pwh[(size_t)C_*C_],    g_pwl[(size_t)C_*C_];     // proj_w
__device__ __nv_bfloat16 g_qh[NKV], g_ql[NKV];
__device__ __nv_bfloat16 g_kh[NKV], g_kl[NKV];
__device__ __nv_bfloat16 g_vh[NKV], g_vl[NKV];
__device__ __nv_bfloat16 g_oh[(size_t)B_*N_*C_],  g_ol[(size_t)B_*N_*C_];   // attn out

// ---------------- helpers ----------------
__device__ __forceinline__ uint32_t pk2(__nv_bfloat16 a, __nv_bfloat16 b) {
    return (uint32_t)__bfloat16_as_ushort(a) | ((uint32_t)__bfloat16_as_ushort(b) << 16);
}
__device__ __forceinline__ void split2(float x, float y, uint32_t& h, uint32_t& l) {
    __nv_bfloat16 hx = __float2bfloat16_rn(x), hy = __float2bfloat16_rn(y);
    h = pk2(hx, hy);
    l = pk2(__float2bfloat16_rn(x - __bfloat162float(hx)),
            __float2bfloat16_rn(y - __bfloat162float(hy)));
}
__device__ __forceinline__ void ldsm4(uint32_t (&r)[4], uint32_t a) {
    asm volatile("ldmatrix.sync.aligned.m8n8.x4.shared.b16 {%0,%1,%2,%3}, [%4];\n"
                 : "=r"(r[0]), "=r"(r[1]), "=r"(r[2]), "=r"(r[3]) : "r"(a));
}
__device__ __forceinline__ void ldsm4t(uint32_t (&r)[4], uint32_t a) {
    asm volatile("ldmatrix.sync.aligned.m8n8.x4.trans.shared.b16 {%0,%1,%2,%3}, [%4];\n"
                 : "=r"(r[0]), "=r"(r[1]), "=r"(r[2]), "=r"(r[3]) : "r"(a));
}
__device__ __forceinline__ void mma16816(float (&c)[4], const uint32_t (&a)[4],
                                         uint32_t b0, uint32_t b1) {
    asm volatile(
        "mma.sync.aligned.m16n8k16.row.col.f32.bf16.bf16.f32 "
        "{%0,%1,%2,%3}, {%4,%5,%6,%7}, {%8,%9}, {%0,%1,%2,%3};\n"
        : "+f"(c[0]), "+f"(c[1]), "+f"(c[2]), "+f"(c[3])
        : "r"(a[0]), "r"(a[1]), "r"(a[2]), "r"(a[3]), "r"(b0), "r"(b1));
}
__device__ __forceinline__ void mma16816p(float (&c)[4], const uint32_t* a,
                                          uint32_t b0, uint32_t b1) {
    asm volatile(
        "mma.sync.aligned.m16n8k16.row.col.f32.bf16.bf16.f32 "
        "{%0,%1,%2,%3}, {%4,%5,%6,%7}, {%8,%9}, {%0,%1,%2,%3};\n"
        : "+f"(c[0]), "+f"(c[1]), "+f"(c[2]), "+f"(c[3])
        : "r"(a[0]), "r"(a[1]), "r"(a[2]), "r"(a[3]), "r"(b0), "r"(b1));
}
__device__ __forceinline__ void cp16(uint32_t dst, const void* src) {
    asm volatile("cp.async.cg.shared.global [%0], [%1], 16;\n" ::"r"(dst), "l"(src));
}

// ---------------------------------------------------------------------------
// Split pass: fp32 -> (hi, lo) bf16. Memory bound, ~32MB total.
// ---------------------------------------------------------------------------
__global__ __launch_bounds__(256) void split_kernel(const float4* __restrict__ src,
                                                    uint2* __restrict__ dh,
                                                    uint2* __restrict__ dl, int n4) {
    int i = blockIdx.x * 256 + threadIdx.x;
    if (i < n4) {
        float4 v = src[i];
        uint32_t h0, l0, h1, l1;
        split2(v.x, v.y, h0, l0);
        split2(v.z, v.w, h1, l1);
        dh[i] = make_uint2(h0, h1);
        dl[i] = make_uint2(l0, l1);
    }
}

// ---------------------------------------------------------------------------
// Dense GEMM (mma.sync, pre-split operands): Out[M,Nc] = A @ W^T.
// Tile BM=128, BN=64, BK=32; 256 thr / 8 warps; warp tile 32x32.
// 3-stage cp.async pipeline, ONE __syncthreads per k-slab; 2 CTAs/SM.
// smem per stage: Ah(10240)+Al(10240)+Bh(5120)+Bl(5120) = 30720B; 3 stages.
// MODE 0: qkv epilogue (bias/scale + split-scatter to q/k/v [B,H,N,D]).
// MODE 1: proj epilogue (+proj_b, fp32 out).
// ---------------------------------------------------------------------------
#define STG 30720
#define AOFF_L 10240
#define BOFF_H 20480
#define BOFF_L 25600

template <int MODE>
__global__ __launch_bounds__(256, 2) void gemm4_kernel(
    const float* __restrict__ qb, const float* __restrict__ vb,
    float* __restrict__ out) {
    extern __shared__ __align__(16) char smraw[];
    const uint32_t sb = (uint32_t)__cvta_generic_to_shared(smraw);
    const int tid = threadIdx.x, lane = tid & 31, wid = tid >> 5;
    const int wm = wid & 3, wn = wid >> 2;           // 4 m-strips x 2 n-strips
    const int m0 = blockIdx.y * 128, n0 = blockIdx.x * 64;

    const __nv_bfloat16* Ah = (MODE == 1) ? g_oh : g_xh;
    const __nv_bfloat16* Al = (MODE == 1) ? g_ol : g_xl;
    const __nv_bfloat16* Bh = (MODE == 1) ? g_pwh : g_wh;
    const __nv_bfloat16* Bl = (MODE == 1) ? g_pwl : g_wl;

    // stage loader: A 512 chunks (2/thr), B 256 chunks (1/thr); chunk = 16B
    auto issue = [&](int ko, int st) {
        const uint32_t base = sb + (uint32_t)st * STG;
        {
            int row = tid >> 2, seg = tid & 3;
            uint32_t doff = (uint32_t)(row * 40 + seg * 8) * 2;
            size_t aoff = (size_t)(m0 + row) * C_ + ko + seg * 8;
            cp16(base + doff, Ah + aoff);
            cp16(base + AOFF_L + doff, Al + aoff);
            int row2 = row + 64;
            uint32_t doff2 = (uint32_t)(row2 * 40 + seg * 8) * 2;
            size_t aoff2 = (size_t)(m0 + row2) * C_ + ko + seg * 8;
            cp16(base + doff2, Ah + aoff2);
            cp16(base + AOFF_L + doff2, Al + aoff2);
            if (row < 64) {
                size_t boff = (size_t)(n0 + row) * C_ + ko + seg * 8;
                cp16(base + BOFF_H + doff, Bh + boff);
                cp16(base + BOFF_L + doff, Bl + boff);
            } else {
                // second half of threads reload B rows 0..63 too? no — split:
            }
        }
        asm volatile("cp.async.commit_group;\n");
    };
    // NOTE: B needs 256 chunks from 256 threads: row = tid>>2 covers 0..63 only
    // for tid<256 with seg 0..3 -> exactly 64 rows x 4 segs = 256 chunks when
    // row = tid>>2 in 0..63. tid in 0..255 gives row 0..63. OK: every thread
    // also issued the (row<64) branch exactly once.

    float c[2][4][4] = {};
    const int arow = wm * 32 + (lane & 15);
    const int acol = (lane >> 4) << 3;
    const int brow = wn * 32 + (lane & 7) + ((lane >> 4) << 3);
    const int bcol = ((lane >> 3) & 1) << 3;

    issue(0, 0);
    issue(32, 1);

    for (int i = 0; i < 32; i++) {
        const int st = i - (i / 3) * 3;
        asm volatile("cp.async.wait_group 1;\n");
        __syncthreads();
        if (i + 2 < 32) issue((i + 2) * 32, (i + 2) - ((i + 2) / 3) * 3);

        const uint32_t base = sb + (uint32_t)st * STG;
#pragma unroll
        for (int s = 0; s < 2; s++) {
            uint32_t ah[2][4], al[2][4], bh[2][4], bl[2][4];
#pragma unroll
            for (int ii = 0; ii < 2; ii++) {
                uint32_t off = (uint32_t)(((arow + ii * 16) * 40 + s * 16 + acol) * 2);
                ldsm4(ah[ii], base + off);
                ldsm4(al[ii], base + AOFF_L + off);
            }
#pragma unroll
            for (int jp = 0; jp < 2; jp++) {
                uint32_t off = (uint32_t)(((brow + jp * 16) * 40 + s * 16 + bcol) * 2);
                ldsm4(bh[jp], base + BOFF_H + off);
                ldsm4(bl[jp], base + BOFF_L + off);
            }
#pragma unroll
            for (int ii = 0; ii < 2; ii++)
#pragma unroll
                for (int j = 0; j < 4; j++) {
                    int jp = j >> 1, o2 = (j & 1) * 2;
                    mma16816(c[ii][j], ah[ii], bh[jp][o2], bh[jp][o2 + 1]);
                    mma16816(c[ii][j], al[ii], bh[jp][o2], bh[jp][o2 + 1]);
                    mma16816(c[ii][j], ah[ii], bl[jp][o2], bl[jp][o2 + 1]);
                }
        }
    }

    // epilogue
#pragma unroll
    for (int i = 0; i < 2; i++) {
#pragma unroll
        for (int rr = 0; rr < 2; rr++) {
            const int m = m0 + wm * 32 + i * 16 + (lane >> 2) + rr * 8;
#pragma unroll
            for (int j = 0; j < 4; j++) {
                const int col = n0 + wn * 32 + j * 8 + 2 * (lane & 3);
                float v0 = c[i][j][rr * 2 + 0], v1 = c[i][j][rr * 2 + 1];
                if (MODE == 1) {
                    *(float2*)(out + (size_t)m * C_ + col) =
                        make_float2(v0 + qb[col], v1 + qb[col + 1]);
                } else {
                    const int which = col >> 10, ch = col & 1023;
                    const int hh = ch >> 6, d = ch & 63;
                    if (which == 0) {
                        v0 = (v0 + qb[ch]) * SCALE_;
                        v1 = (v1 + qb[ch + 1]) * SCALE_;
                    } else if (which == 2) {
                        v0 += vb[ch];
                        v1 += vb[ch + 1];
                    }
                    uint32_t h, l;
                    split2(v0, v1, h, l);
                    const int bb = m >> 11, nn = m & (N_ - 1);
                    size_t off = ((size_t)(bb * H_ + hh) * N_ + nn) * D_ + d;
                    __nv_bfloat16 *dh = (which == 0) ? g_qh : (which == 1 ? g_kh : g_vh);
                    __nv_bfloat16 *dl = (which == 0) ? g_ql : (which == 1 ? g_kl : g_vl);
                    *(uint32_t*)(dh + off) = h;
                    *(uint32_t*)(dl + off) = l;
                }
            }
        }
    }
}

// ---------------------------------------------------------------------------
// Fused flash attention, bf16-split mma.sync (unchanged from R5 pass).
// Grid (B*H, N/128), 256 thr / 8 warps; warp = 16 q-rows; 64-key tiles,
// cp.async double-buffered K/V (hi/lo); bias prefetched to registers.
// ---------------------------------------------------------------------------
#define KVB 4608  // 64*72 elements
__global__ __launch_bounds__(256, 1) void attn_kernel(const float* __restrict__ bias) {
    extern __shared__ __nv_bfloat16 sm[];
    const uint32_t sb = (uint32_t)__cvta_generic_to_shared(sm);
    const int tid = threadIdx.x, lane = tid & 31, wid = tid >> 5;
    const int bh = blockIdx.x, hh = bh & (H_ - 1), bb = bh >> 4;
    const int q0 = blockIdx.y * 128, wrow = wid * 16;

    const __nv_bfloat16* qhp = g_qh + ((size_t)bh * N_ + q0) * D_;
    const __nv_bfloat16* qlp = g_ql + ((size_t)bh * N_ + q0) * D_;
    const __nv_bfloat16* khp = g_kh + (size_t)bh * N_ * D_;
    const __nv_bfloat16* klp = g_kl + (size_t)bh * N_ * D_;
    const __nv_bfloat16* vhp = g_vh + (size_t)bh * N_ * D_;
    const __nv_bfloat16* vlp = g_vl + (size_t)bh * N_ * D_;
    const float* bp0 =
        bias + ((size_t)hh * N_ + q0 + wrow + (lane >> 2)) * N_ + 2 * (lane & 3);
    const float* bp1 = bp0 + 8 * N_;

#pragma unroll
    for (int t = 0; t < 8; t++) {
        int idx = tid + t * 256, row = idx >> 4, seg = idx & 15;
        *(uint2*)&sm[row * 72 + seg * 4] = *(const uint2*)(qhp + row * D_ + seg * 4);
        *(uint2*)&sm[9216 + row * 72 + seg * 4] = *(const uint2*)(qlp + row * D_ + seg * 4);
    }

#define ISSUE_KV(KT, BUF)                                                        \
    {                                                                            \
        _Pragma("unroll") for (int t = 0; t < 2; t++) {                          \
            int chn = tid + t * 256, row = chn >> 3, seg = chn & 7;              \
            uint32_t doff = sb + (18432 + (BUF)*18432 + row * 72 + seg * 8) * 2; \
            size_t soff = (size_t)((KT) + row) * D_ + seg * 8;                   \
            cp16(doff, khp + soff);                                              \
            cp16(doff + KVB * 2, klp + soff);                                    \
            cp16(doff + 2 * KVB * 2, vhp + soff);                                \
            cp16(doff + 3 * KVB * 2, vlp + soff);                                \
        }                                                                        \
        asm volatile("cp.async.commit_group;\n");                                \
    }

    ISSUE_KV(0, 0);
    __syncthreads();

    uint32_t qh[4][4], ql[4][4];
    {
        const uint32_t aq = sb + ((wrow + (lane & 15)) * 72 + ((lane >> 4) << 3)) * 2;
#pragma unroll
        for (int kc = 0; kc < 4; kc++) {
            ldsm4(qh[kc], aq + kc * 32);
            ldsm4(ql[kc], aq + 9216 * 2 + kc * 32);
        }
    }

    float m0 = -1e30f, m1 = -1e30f, l0 = 0.f, l1 = 0.f;
    float o[8][4] = {};
    const int krow = (lane & 7) + ((lane >> 4) << 3);
    const int kcol = ((lane >> 3) & 1) << 3;
    const int vrow = (lane & 7) + (((lane >> 3) & 1) << 3);
    const int vcol = (lane >> 4) << 3;

    for (int t = 0; t < N_ / 64; t++) {
        const int kt = t * 64, buf = t & 1;

        float2 ba[8], bc[8];
#pragma unroll
        for (int j = 0; j < 8; j++) {
            ba[j] = *(const float2*)(bp0 + kt + j * 8);
            bc[j] = *(const float2*)(bp1 + kt + j * 8);
        }

        __syncthreads();
        if (t + 1 < N_ / 64) {
            ISSUE_KV(kt + 64, buf ^ 1);
            asm volatile("cp.async.wait_group 1;\n");
        } else {
            asm volatile("cp.async.wait_group 0;\n");
        }
        __syncthreads();
        const uint32_t kvb = sb + (18432 + buf * 18432) * 2;

        float s[8][4] = {};
#pragma unroll
        for (int kc = 0; kc < 4; kc++)
#pragma unroll
            for (int g = 0; g < 4; g++) {
                uint32_t kh[4], kl[4];
                uint32_t ka = kvb + (uint32_t)(((g * 16 + krow) * 72 + kc * 16 + kcol) * 2);
                ldsm4(kh, ka);
                ldsm4(kl, ka + KVB * 2);
                mma16816(s[2 * g], qh[kc], kh[0], kh[1]);
                mma16816(s[2 * g + 1], qh[kc], kh[2], kh[3]);
                mma16816(s[2 * g], ql[kc], kh[0], kh[1]);
                mma16816(s[2 * g + 1], ql[kc], kh[2], kh[3]);
                mma16816(s[2 * g], qh[kc], kl[0], kl[1]);
                mma16816(s[2 * g + 1], qh[kc], kl[2], kl[3]);
            }

        float mx0 = -1e30f, mx1 = -1e30f;
#pragma unroll
        for (int j = 0; j < 8; j++) {
            s[j][0] += ba[j].x; s[j][1] += ba[j].y;
            s[j][2] += bc[j].x; s[j][3] += bc[j].y;
            mx0 = fmaxf(mx0, fmaxf(s[j][0], s[j][1]));
            mx1 = fmaxf(mx1, fmaxf(s[j][2], s[j][3]));
        }
        mx0 = fmaxf(mx0, __shfl_xor_sync(~0u, mx0, 1));
        mx0 = fmaxf(mx0, __shfl_xor_sync(~0u, mx0, 2));
        mx1 = fmaxf(mx1, __shfl_xor_sync(~0u, mx1, 1));
        mx1 = fmaxf(mx1, __shfl_xor_sync(~0u, mx1, 2));
        float mn0 = fmaxf(m0, mx0), mn1 = fmaxf(m1, mx1);
        float sf0 = __expf(m0 - mn0), sf1 = __expf(m1 - mn1);
        float rs0 = 0.f, rs1 = 0.f;
#pragma unroll
        for (int j = 0; j < 8; j++) {
            s[j][0] = __expf(s[j][0] - mn0);
            s[j][1] = __expf(s[j][1] - mn0);
            s[j][2] = __expf(s[j][2] - mn1);
            s[j][3] = __expf(s[j][3] - mn1);
            rs0 += s[j][0] + s[j][1];
            rs1 += s[j][2] + s[j][3];
        }
        rs0 += __shfl_xor_sync(~0u, rs0, 1);
        rs0 += __shfl_xor_sync(~0u, rs0, 2);
        rs1 += __shfl_xor_sync(~0u, rs1, 1);
        rs1 += __shfl_xor_sync(~0u, rs1, 2);
        l0 = l0 * sf0 + rs0;
        l1 = l1 * sf1 + rs1;
        m0 = mn0;
        m1 = mn1;
#pragma unroll
        for (int j = 0; j < 8; j++) {
            o[j][0] *= sf0; o[j][1] *= sf0;
            o[j][2] *= sf1; o[j][3] *= sf1;
        }

#pragma unroll
        for (int tc = 0; tc < 4; tc++) {
            uint32_t ph[4], pl[4];
            split2(s[2 * tc][0], s[2 * tc][1], ph[0], pl[0]);
            split2(s[2 * tc][2], s[2 * tc][3], ph[1], pl[1]);
            split2(s[2 * tc + 1][0], s[2 * tc + 1][1], ph[2], pl[2]);
            split2(s[2 * tc + 1][2], s[2 * tc + 1][3], ph[3], pl[3]);
#pragma unroll
            for (int dg = 0; dg < 4; dg++) {
                uint32_t vh[4], vl[4];
                uint32_t va = kvb + 2 * KVB * 2 +
                              (uint32_t)(((tc * 16 + vrow) * 72 + dg * 16 + vcol) * 2);
                ldsm4t(vh, va);
                ldsm4t(vl, va + KVB * 2);
                mma16816p(o[2 * dg], ph, vh[0], vh[1]);
                mma16816p(o[2 * dg + 1], ph, vh[2], vh[3]);
                mma16816p(o[2 * dg], pl, vh[0], vh[1]);
                mma16816p(o[2 * dg + 1], pl, vh[2], vh[3]);
                mma16816p(o[2 * dg], ph, vl[0], vl[1]);
                mma16816p(o[2 * dg + 1], ph, vl[2], vl[3]);
            }
        }
    }

    const float inv0 = 1.f / l0, inv1 = 1.f / l1;
    const int nrow = q0 + wrow + (lane >> 2);
    const size_t base0 = (size_t)(bb * N_ + nrow) * C_ + hh * D_;
#pragma unroll
    for (int j = 0; j < 8; j++) {
        const int d = j * 8 + 2 * (lane & 3);
        uint32_t h, l;
        split2(o[j][0] * inv0, o[j][1] * inv0, h, l);
        *(uint32_t*)(g_oh + base0 + d) = h;
        *(uint32_t*)(g_ol + base0 + d) = l;
        split2(o[j][2] * inv1, o[j][3] * inv1, h, l);
        *(uint32_t*)(g_oh + base0 + 8 * C_ + d) = h;
        *(uint32_t*)(g_ol + base0 + 8 * C_ + d) = l;
    }
}

// ---------------------------------------------------------------------------
extern "C" void kernel_launch(void* const* d_in, const int* in_sizes, int n_in,
                              void* d_out, int out_size) {
    const float* x      = (const float*)d_in[0];
    const float* bias   = (const float*)d_in[1];
    const float* qkv_w  = (const float*)d_in[2];
    const float* q_bias = (const float*)d_in[3];
    const float* v_bias = (const float*)d_in[4];
    const float* proj_w = (const float*)d_in[5];
    const float* proj_b = (const float*)d_in[6];
    float* out = (float*)d_out;

    const int gsm = 3 * STG;  // 92160
    cudaFuncSetAttribute(attn_kernel, cudaFuncAttributeMaxDynamicSharedMemorySize,
                         110592);
    cudaFuncSetAttribute(gemm4_kernel<0>, cudaFuncAttributeMaxDynamicSharedMemorySize,
                         gsm);
    cudaFuncSetAttribute(gemm4_kernel<1>, cudaFuncAttributeMaxDynamicSharedMemorySize,
                         gsm);

    void *xh, *xl, *wh, *wl, *pwh, *pwl;
    cudaGetSymbolAddress(&xh, g_xh);   cudaGetSymbolAddress(&xl, g_xl);
    cudaGetSymbolAddress(&wh, g_wh);   cudaGetSymbolAddress(&wl, g_wl);
    cudaGetSymbolAddress(&pwh, g_pwh); cudaGetSymbolAddress(&pwl, g_pwl);

    split_kernel<<<(B_*N_*C_/4 + 255)/256, 256>>>((const float4*)x, (uint2*)xh, (uint2*)xl, B_*N_*C_/4);
    split_kernel<<<(3*C_*C_/4 + 255)/256, 256>>>((const float4*)qkv_w, (uint2*)wh, (uint2*)wl, 3*C_*C_/4);
    split_kernel<<<(C_*C_/4 + 255)/256, 256>>>((const float4*)proj_w, (uint2*)pwh, (uint2*)pwl, C_*C_/4);

    gemm4_kernel<0><<<dim3(48, 32), 256, gsm>>>(q_bias, v_bias, nullptr);
    attn_kernel<<<dim3(B_ * H_, N_ / 128), 256, 110592>>>(bias);
    gemm4_kernel<1><<<dim3(16, 32), 256, gsm>>>(proj_b, nullptr, out);
}